// round 2
// baseline (speedup 1.0000x reference)
#include <cuda_runtime.h>
#include <math.h>

#define EPSF 1e-5f
#define MAX_N (1 << 20)
#define MAX_BLOCKS 65536

// Scratch (no cudaMalloc allowed): per-node 1/alpha, per-block partial sums.
__device__ float g_ainv[MAX_N];
__device__ float g_pP[MAX_BLOCKS];
__device__ float g_pN[MAX_BLOCKS];
__device__ float g_pM[MAX_BLOCKS];

__device__ __forceinline__ float softplusf(float x) {
    // stable: max(x,0) + log1p(exp(-|x|))
    return fmaxf(x, 0.f) + log1pf(expf(-fabsf(x)));
}

// ---------------------------------------------------------------------------
// Kernel 1: per-node 1/max(1-||h_i||^2, eps). Half-warp (16 lanes, float4) per node.
// ---------------------------------------------------------------------------
__global__ __launch_bounds__(256) void norm_kernel(const float4* __restrict__ h4, int N) {
    int lane = threadIdx.x & 31, warp = threadIdx.x >> 5;
    int hw = lane >> 4, l = lane & 15;
    int node = (blockIdx.x * 8 + warp) * 2 + hw;
    float s = 0.f;
    if (node < N) {
        float4 a = __ldg(&h4[(long long)node * 16 + l]);
        s = a.x * a.x + a.y * a.y + a.z * a.z + a.w * a.w;
    }
    s += __shfl_xor_sync(0xffffffffu, s, 8);
    s += __shfl_xor_sync(0xffffffffu, s, 4);
    s += __shfl_xor_sync(0xffffffffu, s, 2);
    s += __shfl_xor_sync(0xffffffffu, s, 1);
    if (node < N && l == 0)
        g_ainv[node] = 1.f / fmaxf(1.f - s, EPSF);
}

// ---------------------------------------------------------------------------
// Kernel 2: fused edge scores + softplus loss + MRR. One warp per pos edge.
// Half-warps (16 lanes x float4 = one 64-float row) process the NPAIRS pairs
// two at a time. Alphas precomputed -> only ||u-v||^2 reduced per pair.
// Specialized on NEG (compile-time) for the hot path.
// ---------------------------------------------------------------------------
template <int NEG>
__global__ __launch_bounds__(256) void edge_kernel_t(
    const float4* __restrict__ h4,
    const int* __restrict__ pos_src, const int* __restrict__ pos_dst,
    const int* __restrict__ neg_src, const int* __restrict__ neg_dst,
    int E_pos)
{
    constexpr int NPAIRS = NEG + 1;
    constexpr int NT = (NPAIRS + 1) / 2;        // half-warp pair-iterations
    const int lane = threadIdx.x & 31;
    const int warp = threadIdx.x >> 5;
    const int hw = lane >> 4;                   // which pair of the current two
    const int l = lane & 15;                    // float4 slot within 64-float row

    float accP = 0.f, accN = 0.f, accM = 0.f;

    for (int e = blockIdx.x * 8 + warp; e < E_pos; e += gridDim.x * 8) {
        // ---- hoist all index loads (broadcast within warp) ----
        int SI[NT], DI[NT];
        bool ACT[NT];
        #pragma unroll
        for (int t = 0; t < NT; ++t) {
            int p = 2 * t + hw;
            ACT[t] = (p < NPAIRS);
            if (!ACT[t]) { SI[t] = 0; DI[t] = 0; continue; }
            if (p == 0) { SI[t] = __ldg(&pos_src[e]); DI[t] = __ldg(&pos_dst[e]); }
            else        { SI[t] = __ldg(&neg_src[e * NEG + p - 1]);
                          DI[t] = __ldg(&neg_dst[e * NEG + p - 1]); }
        }

        // ---- issue all vector gathers up front (max MLP) ----
        float4 A[NT], B[NT];
        #pragma unroll
        for (int t = 0; t < NT; ++t) {
            A[t] = __ldg(&h4[(long long)SI[t] * 16 + l]);
            B[t] = __ldg(&h4[(long long)DI[t] * 16 + l]);
        }

        // ---- per-pair squared distance + score ----
        float sc[NT];
        #pragma unroll
        for (int t = 0; t < NT; ++t) {
            float dx = A[t].x - B[t].x, dy = A[t].y - B[t].y;
            float dz = A[t].z - B[t].z, dw = A[t].w - B[t].w;
            float s = dx * dx + dy * dy + dz * dz + dw * dw;
            s += __shfl_xor_sync(0xffffffffu, s, 8);
            s += __shfl_xor_sync(0xffffffffu, s, 4);
            s += __shfl_xor_sync(0xffffffffu, s, 2);
            s += __shfl_xor_sync(0xffffffffu, s, 1);
            sc[t] = 0.f;
            if (ACT[t]) {
                float ra = __ldg(&g_ainv[SI[t]]);
                float rb = __ldg(&g_ainv[DI[t]]);
                // tg = gamma - 1 = max(2*sq/(alpha*beta), eps)
                float tg = fmaxf(2.f * s * ra * rb, EPSF);
                // arccosh(1+tg) = log1p(tg + sqrt(tg*(tg+2)))  (precision-safe)
                float d = log1pf(tg + sqrtf(tg * (tg + 2.f)));
                sc[t] = d * d;
            }
        }

        // Pair p lives in slot p>>1 of lane (p&1)*16. Pair 0 = pos score.
        float pos = __shfl_sync(0xffffffffu, sc[0], 0);
        float spn = 0.f;
        int cnt = 0;
        #pragma unroll
        for (int j = 1; j < NPAIRS; ++j) {
            float v = __shfl_sync(0xffffffffu, sc[j >> 1], (j & 1) << 4);
            spn += softplusf(-v);
            cnt += (v < pos) ? 1 : 0;       // neg_logit > pos_logit
        }
        accP += softplusf(pos);
        accN += spn;
        accM += 1.f / (float)(cnt + 1);
    }

    __shared__ float sP[8], sN[8], sM[8];
    if (lane == 0) { sP[warp] = accP; sN[warp] = accN; sM[warp] = accM; }
    __syncthreads();
    if (threadIdx.x == 0) {
        float a = 0.f, b = 0.f, c = 0.f;
        #pragma unroll
        for (int w = 0; w < 8; ++w) { a += sP[w]; b += sN[w]; c += sM[w]; }
        g_pP[blockIdx.x] = a;
        g_pN[blockIdx.x] = b;
        g_pM[blockIdx.x] = c;
    }
}

// ---------------------------------------------------------------------------
// Kernel 3: deterministic final reduction (single block, fp64 accumulation).
// ---------------------------------------------------------------------------
__global__ void reduce_kernel(float* out, int nb, double invEp, double invEn, int out_size) {
    __shared__ double sA[512], sB[512], sC[512];
    int tid = threadIdx.x;
    double a = 0.0, b = 0.0, c = 0.0;
    for (int i = tid; i < nb; i += 512) {
        a += (double)g_pP[i];
        b += (double)g_pN[i];
        c += (double)g_pM[i];
    }
    sA[tid] = a; sB[tid] = b; sC[tid] = c;
    __syncthreads();
    for (int k = 256; k > 0; k >>= 1) {
        if (tid < k) { sA[tid] += sA[tid + k]; sB[tid] += sB[tid + k]; sC[tid] += sC[tid + k]; }
        __syncthreads();
    }
    if (tid == 0) {
        out[0] = (float)(sA[0] * invEp + sB[0] * invEn);   // loss
        if (out_size > 1) out[1] = (float)(sC[0] * invEp); // mrr
    }
}

// ---------------------------------------------------------------------------
extern "C" void kernel_launch(void* const* d_in, const int* in_sizes, int n_in,
                              void* d_out, int out_size) {
    const float* h  = (const float*)d_in[0];
    const int* ps   = (const int*)d_in[1];
    const int* pd   = (const int*)d_in[2];
    const int* ns   = (const int*)d_in[3];
    const int* nd   = (const int*)d_in[4];
    // d_in[5] (neg_nums) is a device scalar; derive it host-side instead
    // (graph-capture safe, no sync copies).

    int E_pos = in_sizes[1];
    int E_neg = in_sizes[3];
    int neg_nums = (E_pos > 0) ? (E_neg / E_pos) : 1;
    int N = in_sizes[0] / 64;   // D = 64

    const float4* h4 = (const float4*)h;

    norm_kernel<<<(N + 15) / 16, 256>>>(h4, N);

    int nb = (E_pos + 7) / 8;
    if (nb > MAX_BLOCKS) nb = MAX_BLOCKS;

    switch (neg_nums) {
        case 5: edge_kernel_t<5><<<nb, 256>>>(h4, ps, pd, ns, nd, E_pos); break;
        case 1: edge_kernel_t<1><<<nb, 256>>>(h4, ps, pd, ns, nd, E_pos); break;
        case 2: edge_kernel_t<2><<<nb, 256>>>(h4, ps, pd, ns, nd, E_pos); break;
        case 3: edge_kernel_t<3><<<nb, 256>>>(h4, ps, pd, ns, nd, E_pos); break;
        case 4: edge_kernel_t<4><<<nb, 256>>>(h4, ps, pd, ns, nd, E_pos); break;
        case 6: edge_kernel_t<6><<<nb, 256>>>(h4, ps, pd, ns, nd, E_pos); break;
        case 7: edge_kernel_t<7><<<nb, 256>>>(h4, ps, pd, ns, nd, E_pos); break;
        default: edge_kernel_t<5><<<nb, 256>>>(h4, ps, pd, ns, nd, E_pos); break;
    }

    reduce_kernel<<<1, 512>>>((float*)d_out, nb,
                              1.0 / (double)E_pos, 1.0 / (double)E_neg, out_size);
}

// round 3
// speedup vs baseline: 1.3480x; 1.3480x over previous
#include <cuda_runtime.h>
#include <cuda_fp16.h>
#include <math.h>

#define EPSF 1e-5f
#define MAX_N (1 << 19)          // >= 500000 nodes
#define MAX_BLOCKS 65536

// Scratch (no cudaMalloc allowed).
__device__ uint4 g_hf[MAX_N * 8];     // fp16 table: 64 halves/row = 8 uint4 (64 MB)
__device__ float g_ainv[MAX_N];       // 1/max(1-||h||^2, eps)  (2 MB)
__device__ float g_pP[MAX_BLOCKS];
__device__ float g_pN[MAX_BLOCKS];
__device__ float g_pM[MAX_BLOCKS];

__device__ __forceinline__ float softplusf(float x) {
    return fmaxf(x, 0.f) + log1pf(expf(-fabsf(x)));   // stable
}

__device__ __forceinline__ float pair_score(float s, float ra, float rb) {
    // tg = gamma-1 = max(2*sq/(alpha*beta), eps); arccosh(1+tg) = log1p(tg+sqrt(tg*(tg+2)))
    float tg = fmaxf(2.f * s * ra * rb, EPSF);
    float d = log1pf(tg + sqrtf(tg * (tg + 2.f)));
    return d * d;
}

// ---------------------------------------------------------------------------
// Kernel 1 (fused): per-node 1/alpha (fp32-accurate) + fp16 table conversion.
// Half-warp (16 lanes x float4) per node; writes 16 x uint2 = 128B half row.
// ---------------------------------------------------------------------------
__global__ __launch_bounds__(256) void prep_kernel(const float4* __restrict__ h4, int N) {
    int lane = threadIdx.x & 31, warp = threadIdx.x >> 5;
    int hw = lane >> 4, l = lane & 15;
    int node = (blockIdx.x * 8 + warp) * 2 + hw;
    if (node >= N) return;
    float4 a = __ldg(&h4[(long long)node * 16 + l]);
    float s = a.x * a.x + a.y * a.y + a.z * a.z + a.w * a.w;
    s += __shfl_xor_sync(0xffffffffu, s, 8);
    s += __shfl_xor_sync(0xffffffffu, s, 4);
    s += __shfl_xor_sync(0xffffffffu, s, 2);
    s += __shfl_xor_sync(0xffffffffu, s, 1);
    __half2 h01 = __floats2half2_rn(a.x, a.y);
    __half2 h23 = __floats2half2_rn(a.z, a.w);
    uint2* out = (uint2*)g_hf;
    out[node * 16 + l] = make_uint2(*(const unsigned*)&h01, *(const unsigned*)&h23);
    if (l == 0) g_ainv[node] = 1.f / fmaxf(1.f - s, EPSF);
}

// ---------------------------------------------------------------------------
// Kernel 2 (NEG==5 fast path): 2 pos-edges per warp. 12 pairs map exactly onto
// 3 iterations x 4 eight-lane groups (zero idle lanes). fp16 gathers (128B/pair).
// ---------------------------------------------------------------------------
__global__ __launch_bounds__(256) void edge_kernel5(
    const int* __restrict__ pos_src, const int* __restrict__ pos_dst,
    const int* __restrict__ neg_src, const int* __restrict__ neg_dst,
    int E_pos)
{
    const int lane = threadIdx.x & 31;
    const int warp = threadIdx.x >> 5;
    const int g = lane >> 3;            // 8-lane group: 0..3
    const int k = lane & 7;             // uint4 slot within 128B row
    const int Epair = (E_pos + 1) >> 1;
    const uint4* __restrict__ tab = g_hf;

    float accP = 0.f, accN = 0.f, accM = 0.f;

    for (int e2 = blockIdx.x * 8 + warp; e2 < Epair; e2 += gridDim.x * 8) {
        const int e0 = 2 * e2;
        const int e1 = 2 * e2 + 1;
        const bool act1 = (e1 < E_pos);
        const int e1s = act1 ? e1 : e0;   // safe index

        // ---- indices for this lane's 3 pairs (P = t*4 + g) ----
        int SI[3], DI[3];
        #pragma unroll
        for (int t = 0; t < 3; ++t) {
            int P = t * 4 + g;
            int e = (P < 6) ? e0 : e1s;
            int q = (P < 6) ? P : P - 6;
            if (q == 0) { SI[t] = __ldg(&pos_src[e]);         DI[t] = __ldg(&pos_dst[e]); }
            else        { SI[t] = __ldg(&neg_src[e * 5 + q - 1]);
                          DI[t] = __ldg(&neg_dst[e * 5 + q - 1]); }
        }

        // ---- all 6 vector gathers + 6 ainv gathers up front (max MLP) ----
        uint4 A[3], B[3];
        float RA[3], RB[3];
        #pragma unroll
        for (int t = 0; t < 3; ++t) {
            A[t] = __ldg(&tab[SI[t] * 8 + k]);
            B[t] = __ldg(&tab[DI[t] * 8 + k]);
            RA[t] = __ldg(&g_ainv[SI[t]]);
            RB[t] = __ldg(&g_ainv[DI[t]]);
        }

        // ---- per-pair squared distance (8-lane butterfly) + score ----
        float sc[3];
        #pragma unroll
        for (int t = 0; t < 3; ++t) {
            float s = 0.f;
            const unsigned* pa = &A[t].x;
            const unsigned* pb = &B[t].x;
            #pragma unroll
            for (int j = 0; j < 4; ++j) {
                __half2 da = __hsub2(*(const __half2*)&pa[j], *(const __half2*)&pb[j]);
                float2 f = __half22float2(da);
                s = fmaf(f.x, f.x, s);
                s = fmaf(f.y, f.y, s);
            }
            s += __shfl_xor_sync(0xffffffffu, s, 4);
            s += __shfl_xor_sync(0xffffffffu, s, 2);
            s += __shfl_xor_sync(0xffffffffu, s, 1);
            sc[t] = pair_score(s, RA[t], RB[t]);
        }

        // ---- gather the 12 scores (pair P in lane P%4 * 8, slot P/4) ----
        float v[12];
        #pragma unroll
        for (int P = 0; P < 12; ++P)
            v[P] = __shfl_sync(0xffffffffu, sc[P >> 2], (P & 3) << 3);

        // edge 0: pairs 0..5 ; edge 1: pairs 6..11 (pair 0 of each = positive)
        float p0 = v[0], p1 = v[6];
        float spn = 0.f;
        int c0 = 0, c1 = 0;
        #pragma unroll
        for (int j = 1; j < 6; ++j) {
            spn += softplusf(-v[j]);
            c0 += (v[j] < p0) ? 1 : 0;
        }
        float spn1 = 0.f;
        #pragma unroll
        for (int j = 7; j < 12; ++j) {
            spn1 += softplusf(-v[j]);
            c1 += (v[j] < p1) ? 1 : 0;
        }
        accP += softplusf(p0);
        accN += spn;
        accM += 1.f / (float)(c0 + 1);
        if (act1) {
            accP += softplusf(p1);
            accN += spn1;
            accM += 1.f / (float)(c1 + 1);
        }
    }

    __shared__ float sP[8], sN[8], sM[8];
    if (lane == 0) { sP[warp] = accP; sN[warp] = accN; sM[warp] = accM; }
    __syncthreads();
    if (threadIdx.x == 0) {
        float a = 0.f, b = 0.f, c = 0.f;
        #pragma unroll
        for (int w = 0; w < 8; ++w) { a += sP[w]; b += sN[w]; c += sM[w]; }
        g_pP[blockIdx.x] = a; g_pN[blockIdx.x] = b; g_pM[blockIdx.x] = c;
    }
}

// ---------------------------------------------------------------------------
// Generic fallback (any NEG): one edge per warp, fp16 table, 16-lane groups.
// ---------------------------------------------------------------------------
template <int NEG>
__global__ __launch_bounds__(256) void edge_kernel_t(
    const int* __restrict__ pos_src, const int* __restrict__ pos_dst,
    const int* __restrict__ neg_src, const int* __restrict__ neg_dst,
    int E_pos)
{
    constexpr int NPAIRS = NEG + 1;
    constexpr int NT = (NPAIRS + 3) / 4;     // 8-lane groups: 4 pairs per iter
    const int lane = threadIdx.x & 31;
    const int warp = threadIdx.x >> 5;
    const int g = lane >> 3, k = lane & 7;
    const uint4* __restrict__ tab = g_hf;

    float accP = 0.f, accN = 0.f, accM = 0.f;

    for (int e = blockIdx.x * 8 + warp; e < E_pos; e += gridDim.x * 8) {
        float sc[NT];
        #pragma unroll
        for (int t = 0; t < NT; ++t) {
            int P = t * 4 + g;
            bool act = (P < NPAIRS);
            int si = 0, di = 0;
            if (act) {
                if (P == 0) { si = __ldg(&pos_src[e]); di = __ldg(&pos_dst[e]); }
                else        { si = __ldg(&neg_src[e * NEG + P - 1]);
                              di = __ldg(&neg_dst[e * NEG + P - 1]); }
            }
            uint4 A = __ldg(&tab[si * 8 + k]);
            uint4 B = __ldg(&tab[di * 8 + k]);
            float s = 0.f;
            const unsigned* pa = &A.x;
            const unsigned* pb = &B.x;
            #pragma unroll
            for (int j = 0; j < 4; ++j) {
                __half2 da = __hsub2(*(const __half2*)&pa[j], *(const __half2*)&pb[j]);
                float2 f = __half22float2(da);
                s = fmaf(f.x, f.x, s);
                s = fmaf(f.y, f.y, s);
            }
            s += __shfl_xor_sync(0xffffffffu, s, 4);
            s += __shfl_xor_sync(0xffffffffu, s, 2);
            s += __shfl_xor_sync(0xffffffffu, s, 1);
            sc[t] = act ? pair_score(s, __ldg(&g_ainv[si]), __ldg(&g_ainv[di])) : 0.f;
        }
        float pos = __shfl_sync(0xffffffffu, sc[0], 0);
        float spn = 0.f; int cnt = 0;
        #pragma unroll
        for (int j = 1; j < NPAIRS; ++j) {
            float vv = __shfl_sync(0xffffffffu, sc[j >> 2], (j & 3) << 3);
            spn += softplusf(-vv);
            cnt += (vv < pos) ? 1 : 0;
        }
        accP += softplusf(pos);
        accN += spn;
        accM += 1.f / (float)(cnt + 1);
    }

    __shared__ float sP[8], sN[8], sM[8];
    if (lane == 0) { sP[warp] = accP; sN[warp] = accN; sM[warp] = accM; }
    __syncthreads();
    if (threadIdx.x == 0) {
        float a = 0.f, b = 0.f, c = 0.f;
        #pragma unroll
        for (int w = 0; w < 8; ++w) { a += sP[w]; b += sN[w]; c += sM[w]; }
        g_pP[blockIdx.x] = a; g_pN[blockIdx.x] = b; g_pM[blockIdx.x] = c;
    }
}

// ---------------------------------------------------------------------------
// Kernel 3: deterministic final reduction (single block, fp64).
// ---------------------------------------------------------------------------
__global__ void reduce_kernel(float* out, int nb, double invEp, double invEn, int out_size) {
    __shared__ double sA[512], sB[512], sC[512];
    int tid = threadIdx.x;
    double a = 0.0, b = 0.0, c = 0.0;
    for (int i = tid; i < nb; i += 512) {
        a += (double)g_pP[i]; b += (double)g_pN[i]; c += (double)g_pM[i];
    }
    sA[tid] = a; sB[tid] = b; sC[tid] = c;
    __syncthreads();
    for (int k = 256; k > 0; k >>= 1) {
        if (tid < k) { sA[tid] += sA[tid + k]; sB[tid] += sB[tid + k]; sC[tid] += sC[tid + k]; }
        __syncthreads();
    }
    if (tid == 0) {
        out[0] = (float)(sA[0] * invEp + sB[0] * invEn);
        if (out_size > 1) out[1] = (float)(sC[0] * invEp);
    }
}

// ---------------------------------------------------------------------------
extern "C" void kernel_launch(void* const* d_in, const int* in_sizes, int n_in,
                              void* d_out, int out_size) {
    const float* h  = (const float*)d_in[0];
    const int* ps   = (const int*)d_in[1];
    const int* pd   = (const int*)d_in[2];
    const int* ns   = (const int*)d_in[3];
    const int* nd   = (const int*)d_in[4];

    int E_pos = in_sizes[1];
    int E_neg = in_sizes[3];
    int neg_nums = (E_pos > 0) ? (E_neg / E_pos) : 1;
    int N = in_sizes[0] / 64;   // D = 64

    prep_kernel<<<(N + 15) / 16, 256>>>((const float4*)h, N);

    int nb;
    if (neg_nums == 5) {
        int Epair = (E_pos + 1) / 2;
        nb = (Epair + 7) / 8;
        if (nb > MAX_BLOCKS) nb = MAX_BLOCKS;
        edge_kernel5<<<nb, 256>>>(ps, pd, ns, nd, E_pos);
    } else {
        nb = (E_pos + 7) / 8;
        if (nb > MAX_BLOCKS) nb = MAX_BLOCKS;
        switch (neg_nums) {
            case 1: edge_kernel_t<1><<<nb, 256>>>(ps, pd, ns, nd, E_pos); break;
            case 2: edge_kernel_t<2><<<nb, 256>>>(ps, pd, ns, nd, E_pos); break;
            case 3: edge_kernel_t<3><<<nb, 256>>>(ps, pd, ns, nd, E_pos); break;
            case 4: edge_kernel_t<4><<<nb, 256>>>(ps, pd, ns, nd, E_pos); break;
            case 6: edge_kernel_t<6><<<nb, 256>>>(ps, pd, ns, nd, E_pos); break;
            case 7: edge_kernel_t<7><<<nb, 256>>>(ps, pd, ns, nd, E_pos); break;
            default: edge_kernel_t<8><<<nb, 256>>>(ps, pd, ns, nd, E_pos); break;
        }
    }

    reduce_kernel<<<1, 512>>>((float*)d_out, nb,
                              1.0 / (double)E_pos, 1.0 / (double)E_neg, out_size);
}

// round 5
// speedup vs baseline: 1.5881x; 1.1781x over previous
#include <cuda_runtime.h>
#include <cuda_fp16.h>
#include <math.h>

#define EPSF 1e-5f
#define MAX_N (1 << 19)          // >= 500000 nodes
#define MAX_BLOCKS 65536

// Scratch (no cudaMalloc allowed).
__device__ uint4 g_hf[MAX_N * 8];     // fp16 table: 64 halves/row = 8 uint4 (64 MB)
__device__ float g_pP[MAX_BLOCKS];
__device__ float g_pN[MAX_BLOCKS];
__device__ float g_pM[MAX_BLOCKS];

__device__ __forceinline__ float softplusf(float x) {
    return fmaxf(x, 0.f) + log1pf(expf(-fabsf(x)));   // stable
}

__device__ __forceinline__ float score_from(float s, float su, float sv) {
    // alpha = max(1-||u||^2, eps); tg = gamma-1 = max(2*s/(au*av), eps)
    float au = fmaxf(1.f - su, EPSF);
    float av = fmaxf(1.f - sv, EPSF);
    float tg = fmaxf(2.f * s / (au * av), EPSF);
    // arccosh(1+tg) = log1p(tg + sqrt(tg*(tg+2)))  (precision-safe near 1)
    float d = log1pf(tg + sqrtf(tg * (tg + 2.f)));
    return d * d;
}

// ---------------------------------------------------------------------------
// Kernel 1: pure streaming fp32 -> fp16 table conversion (one float4/thread).
// ---------------------------------------------------------------------------
__global__ __launch_bounds__(256) void prep_kernel(const float4* __restrict__ h4, int n4) {
    int idx = blockIdx.x * 256 + threadIdx.x;
    if (idx >= n4) return;
    float4 a = __ldg(&h4[idx]);
    __half2 h01 = __floats2half2_rn(a.x, a.y);
    __half2 h23 = __floats2half2_rn(a.z, a.w);
    ((uint2*)g_hf)[idx] = make_uint2(*(const unsigned*)&h01, *(const unsigned*)&h23);
}

// ---------------------------------------------------------------------------
// Kernel 2 (NEG==5): 2 pos-edges per warp; 12 pairs = 3 iters x 4 eight-lane
// groups (zero idle lanes). Norms computed in-register (no ainv gathers).
// Distributed epilogue: each lane softpluses its own pairs, 2-step cross-group
// butterfly (all 8 lanes per group hold identical values -> no masking).
// ---------------------------------------------------------------------------
__global__ __launch_bounds__(256) void edge_kernel5(
    const int* __restrict__ pos_src, const int* __restrict__ pos_dst,
    const int* __restrict__ neg_src, const int* __restrict__ neg_dst,
    int E_pos)
{
    const int lane = threadIdx.x & 31;
    const int warp = threadIdx.x >> 5;
    const int g = lane >> 3;            // 8-lane group: 0..3
    const int k = lane & 7;             // uint4 slot within 128B row
    const int Epair = (E_pos + 1) >> 1;
    const uint4* __restrict__ tab = g_hf;

    float accP = 0.f, accN = 0.f, accM = 0.f;

    for (int e2 = blockIdx.x * 8 + warp; e2 < Epair; e2 += gridDim.x * 8) {
        const int e0 = 2 * e2;
        const int e1 = 2 * e2 + 1;
        const bool act1 = (e1 < E_pos);
        const int e1s = act1 ? e1 : e0;   // safe index

        // ---- indices for this lane's 3 pairs (P = t*4 + g) ----
        int SI[3], DI[3];
        #pragma unroll
        for (int t = 0; t < 3; ++t) {
            int P = t * 4 + g;
            int e = (P < 6) ? e0 : e1s;
            int q = (P < 6) ? P : P - 6;
            if (q == 0) { SI[t] = __ldg(&pos_src[e]);          DI[t] = __ldg(&pos_dst[e]); }
            else        { SI[t] = __ldg(&neg_src[e * 5 + q - 1]);
                          DI[t] = __ldg(&neg_dst[e * 5 + q - 1]); }
        }

        // ---- all 6 warp-wide vector gathers up front (max MLP) ----
        uint4 A[3], B[3];
        #pragma unroll
        for (int t = 0; t < 3; ++t) {
            A[t] = __ldg(&tab[SI[t] * 8 + k]);
            B[t] = __ldg(&tab[DI[t] * 8 + k]);
        }

        // ---- per-pair: ||u-v||^2, ||u||^2, ||v||^2 via one 3-chain butterfly ----
        float sc[3];
        #pragma unroll
        for (int t = 0; t < 3; ++t) {
            float s = 0.f, su = 0.f, sv = 0.f;
            const unsigned* pa = &A[t].x;
            const unsigned* pb = &B[t].x;
            #pragma unroll
            for (int j = 0; j < 4; ++j) {
                float2 fa = __half22float2(*(const __half2*)&pa[j]);
                float2 fb = __half22float2(*(const __half2*)&pb[j]);
                float dx = fa.x - fb.x, dy = fa.y - fb.y;
                s  = fmaf(dx, dx, s);   s  = fmaf(dy, dy, s);
                su = fmaf(fa.x, fa.x, su); su = fmaf(fa.y, fa.y, su);
                sv = fmaf(fb.x, fb.x, sv); sv = fmaf(fb.y, fb.y, sv);
            }
            #pragma unroll
            for (int d = 4; d > 0; d >>= 1) {
                s  += __shfl_xor_sync(0xffffffffu, s,  d);
                su += __shfl_xor_sync(0xffffffffu, su, d);
                sv += __shfl_xor_sync(0xffffffffu, sv, d);
            }
            sc[t] = score_from(s, su, sv);
        }

        // ---- distributed epilogue ----
        // Pair map: t=0 -> P=g (P==0 pos of edge0); t=1 -> P=4+g (P==6 pos of
        // edge1 at g==2); t=2 -> P=8+g (all edge1 negs).
        float p0 = __shfl_sync(0xffffffffu, sc[0], 0);    // pair 0
        float p1 = __shfl_sync(0xffffffffu, sc[1], 16);   // pair 6 (t=1, g=2)

        bool pos0 = (g == 0);     // t=0 is positive pair
        bool pos1 = (g == 2);     // t=1 is positive pair
        float sp0 = softplusf(pos0 ? sc[0] : -sc[0]);
        float sp1 = softplusf(pos1 ? sc[1] : -sc[1]);
        float sp2 = softplusf(-sc[2]);

        float aP = 0.f, aN = 0.f;
        int cc = 0;
        // t=0: P=g -> edge0; pos if g==0 else neg
        if (pos0) aP += sp0;
        else      { aN += sp0; cc += (sc[0] < p0) ? 1 : 0; }
        // t=1: P=4+g; g<2 -> edge0 negs (P=4,5); g==2 -> pos of edge1; g==3 -> neg of edge1 (P=7)
        if (g < 2)        { aN += sp1; cc += (sc[1] < p0) ? 1 : 0; }
        else if (pos1)    { if (act1) aP += sp1; }
        else              { if (act1) { aN += sp1; cc += (sc[1] < p1) ? 64 : 0; } }
        // t=2: P=8+g -> edge1 negs
        if (act1) { aN += sp2; cc += (sc[2] < p1) ? 64 : 0; }

        // cross-group butterfly (xor 8,16): lanes {i, i^8, i^16, i^24} are the
        // 4 groups at fixed k; values identical within a group.
        #pragma unroll
        for (int d = 8; d <= 16; d <<= 1) {
            aP += __shfl_xor_sync(0xffffffffu, aP, d);
            aN += __shfl_xor_sync(0xffffffffu, aN, d);
            cc += __shfl_xor_sync(0xffffffffu, cc, d);
        }
        int c0 = cc & 63, c1 = cc >> 6;
        accP += aP;
        accN += aN;
        accM += 1.f / (float)(c0 + 1) + (act1 ? 1.f / (float)(c1 + 1) : 0.f);
    }

    __shared__ float sP[8], sN[8], sM[8];
    if (lane == 0) { sP[warp] = accP; sN[warp] = accN; sM[warp] = accM; }
    __syncthreads();
    if (threadIdx.x == 0) {
        float a = 0.f, b = 0.f, c = 0.f;
        #pragma unroll
        for (int w = 0; w < 8; ++w) { a += sP[w]; b += sN[w]; c += sM[w]; }
        g_pP[blockIdx.x] = a; g_pN[blockIdx.x] = b; g_pM[blockIdx.x] = c;
    }
}

// ---------------------------------------------------------------------------
// Generic fallback (any NEG): one edge per warp, in-register norms.
// ---------------------------------------------------------------------------
template <int NEG>
__global__ __launch_bounds__(256) void edge_kernel_t(
    const int* __restrict__ pos_src, const int* __restrict__ pos_dst,
    const int* __restrict__ neg_src, const int* __restrict__ neg_dst,
    int E_pos)
{
    constexpr int NPAIRS = NEG + 1;
    constexpr int NT = (NPAIRS + 3) / 4;
    const int lane = threadIdx.x & 31;
    const int warp = threadIdx.x >> 5;
    const int g = lane >> 3, k = lane & 7;
    const uint4* __restrict__ tab = g_hf;

    float accP = 0.f, accN = 0.f, accM = 0.f;

    for (int e = blockIdx.x * 8 + warp; e < E_pos; e += gridDim.x * 8) {
        float sc[NT];
        #pragma unroll
        for (int t = 0; t < NT; ++t) {
            int P = t * 4 + g;
            bool act = (P < NPAIRS);
            int si = 0, di = 0;
            if (act) {
                if (P == 0) { si = __ldg(&pos_src[e]); di = __ldg(&pos_dst[e]); }
                else        { si = __ldg(&neg_src[e * NEG + P - 1]);
                              di = __ldg(&neg_dst[e * NEG + P - 1]); }
            }
            uint4 A = __ldg(&tab[si * 8 + k]);
            uint4 B = __ldg(&tab[di * 8 + k]);
            float s = 0.f, su = 0.f, sv = 0.f;
            const unsigned* pa = &A.x;
            const unsigned* pb = &B.x;
            #pragma unroll
            for (int j = 0; j < 4; ++j) {
                float2 fa = __half22float2(*(const __half2*)&pa[j]);
                float2 fb = __half22float2(*(const __half2*)&pb[j]);
                float dx = fa.x - fb.x, dy = fa.y - fb.y;
                s  = fmaf(dx, dx, s);   s  = fmaf(dy, dy, s);
                su = fmaf(fa.x, fa.x, su); su = fmaf(fa.y, fa.y, su);
                sv = fmaf(fb.x, fb.x, sv); sv = fmaf(fb.y, fb.y, sv);
            }
            #pragma unroll
            for (int d = 4; d > 0; d >>= 1) {
                s  += __shfl_xor_sync(0xffffffffu, s,  d);
                su += __shfl_xor_sync(0xffffffffu, su, d);
                sv += __shfl_xor_sync(0xffffffffu, sv, d);
            }
            sc[t] = act ? score_from(s, su, sv) : 0.f;
        }
        float pos = __shfl_sync(0xffffffffu, sc[0], 0);
        float spn = 0.f; int cnt = 0;
        #pragma unroll
        for (int j = 1; j < NPAIRS; ++j) {
            float vv = __shfl_sync(0xffffffffu, sc[j >> 2], (j & 3) << 3);
            spn += softplusf(-vv);
            cnt += (vv < pos) ? 1 : 0;
        }
        accP += softplusf(pos);
        accN += spn;
        accM += 1.f / (float)(cnt + 1);
    }

    __shared__ float sP[8], sN[8], sM[8];
    if (lane == 0) { sP[warp] = accP; sN[warp] = accN; sM[warp] = accM; }
    __syncthreads();
    if (threadIdx.x == 0) {
        float a = 0.f, b = 0.f, c = 0.f;
        #pragma unroll
        for (int w = 0; w < 8; ++w) { a += sP[w]; b += sN[w]; c += sM[w]; }
        g_pP[blockIdx.x] = a; g_pN[blockIdx.x] = b; g_pM[blockIdx.x] = c;
    }
}

// ---------------------------------------------------------------------------
// Kernel 3: deterministic final reduction (single block, fp64).
// ---------------------------------------------------------------------------
__global__ void reduce_kernel(float* out, int nb, double invEp, double invEn, int out_size) {
    __shared__ double sA[512], sB[512], sC[512];
    int tid = threadIdx.x;
    double a = 0.0, b = 0.0, c = 0.0;
    for (int i = tid; i < nb; i += 512) {
        a += (double)g_pP[i]; b += (double)g_pN[i]; c += (double)g_pM[i];
    }
    sA[tid] = a; sB[tid] = b; sC[tid] = c;
    __syncthreads();
    for (int k = 256; k > 0; k >>= 1) {
        if (tid < k) { sA[tid] += sA[tid + k]; sB[tid] += sB[tid + k]; sC[tid] += sC[tid + k]; }
        __syncthreads();
    }
    if (tid == 0) {
        out[0] = (float)(sA[0] * invEp + sB[0] * invEn);
        if (out_size > 1) out[1] = (float)(sC[0] * invEp);
    }
}

// ---------------------------------------------------------------------------
extern "C" void kernel_launch(void* const* d_in, const int* in_sizes, int n_in,
                              void* d_out, int out_size) {
    const float* h  = (const float*)d_in[0];
    const int* ps   = (const int*)d_in[1];
    const int* pd   = (const int*)d_in[2];
    const int* ns   = (const int*)d_in[3];
    const int* nd   = (const int*)d_in[4];

    int E_pos = in_sizes[1];
    int E_neg = in_sizes[3];
    int neg_nums = (E_pos > 0) ? (E_neg / E_pos) : 1;
    int n4 = in_sizes[0] / 4;     // number of float4 in the table

    prep_kernel<<<(n4 + 255) / 256, 256>>>((const float4*)h, n4);

    int nb;
    if (neg_nums == 5) {
        int Epair = (E_pos + 1) / 2;
        nb = (Epair + 7) / 8;
        if (nb > MAX_BLOCKS) nb = MAX_BLOCKS;
        edge_kernel5<<<nb, 256>>>(ps, pd, ns, nd, E_pos);
    } else {
        nb = (E_pos + 7) / 8;
        if (nb > MAX_BLOCKS) nb = MAX_BLOCKS;
        switch (neg_nums) {
            case 1: edge_kernel_t<1><<<nb, 256>>>(ps, pd, ns, nd, E_pos); break;
            case 2: edge_kernel_t<2><<<nb, 256>>>(ps, pd, ns, nd, E_pos); break;
            case 3: edge_kernel_t<3><<<nb, 256>>>(ps, pd, ns, nd, E_pos); break;
            case 4: edge_kernel_t<4><<<nb, 256>>>(ps, pd, ns, nd, E_pos); break;
            case 6: edge_kernel_t<6><<<nb, 256>>>(ps, pd, ns, nd, E_pos); break;
            case 7: edge_kernel_t<7><<<nb, 256>>>(ps, pd, ns, nd, E_pos); break;
            default: edge_kernel_t<8><<<nb, 256>>>(ps, pd, ns, nd, E_pos); break;
        }
    }

    reduce_kernel<<<1, 512>>>((float*)d_out, nb,
                              1.0 / (double)E_pos, 1.0 / (double)E_neg, out_size);
}